// round 8
// baseline (speedup 1.0000x reference)
#include <cuda_runtime.h>
#include <math.h>

#define BATCH   16
#define NPB     36864      // boxes per batch = 64*64*9
#define THREADS 1024
#define PER_TH  36         // NPB / THREADS
#define TOPN    300
#define NGT     64
#define TPOS    64
#define NBUCK   4096
#define CHK     512        // NMS chunk size
#define NBAND   16
#define SEGCAP  64

// L2-resident scratch (no cudaMalloc allowed)
__device__ float4             g_boxes[BATCH * NPB];
__device__ unsigned long long g_sorted[BATCH * NPB];

// dynamic smem layout (u32 units)
#define OFF_HIST  0          // u32[4096]
#define OFF_CUM   4096       // u32[4097] (+pad)
#define OFF_BPOS  8200       // u32[4096]
#define OFF_KBOX  12296      // float4[512]
#define OFF_MASK  14344      // u32[512*16]
#define OFF_CBOX  22536      // float4[512]
#define OFF_CAREA 24584      // f32[512]
#define OFF_PERM  25096      // u16[512]
#define OFF_KILL  25352      // u8[1024]  (kA = [0,512), kB = [512,1024))
#define DYN_U32   25608
#define DYN_BYTES (DYN_U32 * 4)

// bucket from descending key30 (monotone coarsening): uniform in score VALUE.
__device__ __forceinline__ unsigned bucket_of(unsigned key30) {
    float s = __uint_as_float(0x3F7FFFFFu - key30);
    unsigned q = (unsigned)__fmul_rn(s, 4096.f);
    if (q > 4095u) q = 4095u;
    return 4095u - q;
}

// area-octave band (classification only; correctness comes from min/max guards)
__device__ __forceinline__ int band_of(float a) {
    int bd = (int)(__float_as_uint(a) >> 23) - 117;
    return bd < 0 ? 0 : (bd > NBAND - 1 ? NBAND - 1 : bd);
}

// Exact-threshold suppression test: guard band + exact division fallback.
__device__ __forceinline__ bool suppress_test(float4 sb, float sa, float4 bx, float ab) {
    float yy1 = fmaxf(sb.x, bx.x);
    float xx1 = fmaxf(sb.y, bx.y);
    float yy2 = fminf(sb.z, bx.z);
    float xx2 = fminf(sb.w, bx.w);
    float ih  = fmaxf(__fsub_rn(yy2, yy1), 0.f);
    float iw  = fmaxf(__fsub_rn(xx2, xx1), 0.f);
    float inter = __fmul_rn(ih, iw);
    float denom = __fadd_rn(__fsub_rn(__fadd_rn(sa, ab), inter), 1e-7f);
    float e = __fmaf_rn(-0.5f, denom, inter);
    float margin = __fmul_rn(denom, 1e-4f);
    if (e < -margin) return false;
    if (e >  margin) return true;
    return __fdiv_rn(inter, denom) >= 0.5f;       // exact reference semantics
}

__global__ void __launch_bounds__(THREADS, 1)
roi_kernel(const float* __restrict__ deltas,
           const float* __restrict__ labels,
           const float* __restrict__ anchors,
           const float* __restrict__ gt,
           float* __restrict__ out)
{
    extern __shared__ unsigned s_dyn[];
    unsigned* s_hist  = s_dyn;
    unsigned* s_cum   = s_dyn + OFF_CUM;
    unsigned* s_bpos  = s_dyn + OFF_BPOS;
    float4*   s_kbox  = (float4*)(s_dyn + OFF_KBOX);
    unsigned* s_mask  = s_dyn + OFF_MASK;
    float4*   s_cbox  = (float4*)(s_dyn + OFF_CBOX);
    float*    s_carea = (float*)(s_dyn + OFF_CAREA);
    unsigned short* s_perm = (unsigned short*)(s_dyn + OFF_PERM);
    unsigned char*  s_kill = (unsigned char*)(s_dyn + OFF_KILL);

    __shared__ float4 s_sel[TOPN];
    __shared__ float  s_sela[TOPN];
    __shared__ float4 s_nms[TOPN];
    __shared__ float  s_merged[TOPN];
    __shared__ int    s_gtbest[TOPN];
    __shared__ float4 s_gt4[NGT];
    __shared__ unsigned s_warp[32];
    __shared__ int    s_ncur, s_M;
    // band index of selected boxes
    __shared__ unsigned short s_bidx[NBAND][304];
    __shared__ int    s_bcnt[NBAND];
    __shared__ float  s_bmin[NBAND], s_bmax[NBAND];
    __shared__ int    s_bh[NBAND], s_bstart[NBAND];
    __shared__ unsigned char s_cband[CHK];

    const int b = blockIdx.x;
    const int t = threadIdx.x;
    const int lane = t & 31, wid = t >> 5;
    const int p    = t & (CHK - 1);   // candidate slot within chunk
    const int grp  = t >> 9;          // 0 or 1

    const float4* anc4 = (const float4*)(anchors) + (size_t)b * NPB;
    const float4* dlt4 = (const float4*)(deltas)  + (size_t)b * NPB;
    const float*  lab  = labels + (size_t)b * NPB;
    float4*             boxes = g_boxes  + (size_t)b * NPB;
    unsigned long long* srt   = g_sorted + (size_t)b * NPB;

    // ================= Phase A: decode + bucket histogram ==================
    #pragma unroll
    for (int c = 0; c < 4; ++c) s_hist[c * 1024 + t] = 0;
    if (t == 0) s_ncur = 0;
    if (t < NBAND) {
        s_bcnt[t] = 0; s_bh[t] = 0;
        s_bmin[t] = 1e30f; s_bmax[t] = -1e30f;
    }
    __syncthreads();

    #pragma unroll 4
    for (int k = 0; k < PER_TH; ++k) {
        int i = t + k * THREADS;
        float4 a = anc4[i];
        float4 d = dlt4[i];
        float ah  = __fsub_rn(a.z, a.x);
        float aw  = __fsub_rn(a.w, a.y);
        float acy = __fadd_rn(a.x, __fmul_rn(0.5f, ah));
        float acx = __fadd_rn(a.y, __fmul_rn(0.5f, aw));
        float h   = __fmul_rn(expf(d.z), ah);
        float w   = __fmul_rn(expf(d.w), aw);
        float cy  = __fadd_rn(__fmul_rn(d.x, ah), acy);
        float cx  = __fadd_rn(__fmul_rn(d.y, aw), acx);
        float y1  = __fsub_rn(cy, __fmul_rn(0.5f, h));
        float x1  = __fsub_rn(cx, __fmul_rn(0.5f, w));
        boxes[i]  = make_float4(y1, x1, __fadd_rn(y1, h), __fadd_rn(x1, w));
        unsigned key30 = 0x3F7FFFFFu - __float_as_uint(lab[i]);
        atomicAdd(&s_hist[bucket_of(key30)], 1u);
    }
    __syncthreads();

    // ================= Phase B: exclusive scan -> cum; bpos = cum ==========
    {
        unsigned v[4], sum = 0;
        #pragma unroll
        for (int j = 0; j < 4; ++j) { v[j] = s_hist[t * 4 + j]; }
        unsigned e[4];
        #pragma unroll
        for (int j = 0; j < 4; ++j) { e[j] = sum; sum += v[j]; }
        unsigned x = sum;
        #pragma unroll
        for (int o = 1; o < 32; o <<= 1) {
            unsigned y = __shfl_up_sync(0xffffffffu, x, o);
            if (lane >= o) x += y;
        }
        if (lane == 31) s_warp[wid] = x;
        __syncthreads();
        if (t < 32) {
            unsigned wsum = s_warp[t], xx = wsum;
            #pragma unroll
            for (int o = 1; o < 32; o <<= 1) {
                unsigned y = __shfl_up_sync(0xffffffffu, xx, o);
                if (t >= o) xx += y;
            }
            s_warp[t] = xx - wsum;
        }
        __syncthreads();
        unsigned prefix = s_warp[wid] + (x - sum);
        #pragma unroll
        for (int j = 0; j < 4; ++j) {
            s_cum[t * 4 + j]  = prefix + e[j];
            s_bpos[t * 4 + j] = prefix + e[j];
        }
        if (t == THREADS - 1) s_cum[NBUCK] = prefix + sum;
        __syncthreads();
    }

    // ========= Phase A2: counting-sort scatter (recompute keys from lab) ===
    #pragma unroll 4
    for (int k = 0; k < PER_TH; ++k) {
        int i = t + k * THREADS;
        unsigned key30 = 0x3F7FFFFFu - __float_as_uint(lab[i]);
        unsigned bk = bucket_of(key30);
        unsigned slot = atomicAdd(&s_bpos[bk], 1u);
        srt[slot] = ((unsigned long long)key30 << 16) | (unsigned)i;
    }
    __syncthreads();

    // ========= Phase B2: per-bucket segment sort via local array (MLP) =====
    #pragma unroll
    for (int c = 0; c < 4; ++c) {
        int bk = t + c * THREADS;
        int lo = (int)s_cum[bk], hi = (int)s_cum[bk + 1];
        int n = hi - lo;
        if (n > 1) {
            if (n <= SEGCAP) {
                unsigned long long loc[SEGCAP];
                for (int i2 = 0; i2 < n; ++i2) loc[i2] = srt[lo + i2];
                for (int i2 = 1; i2 < n; ++i2) {
                    unsigned long long v = loc[i2];
                    int j2 = i2 - 1;
                    while (j2 >= 0 && loc[j2] > v) { loc[j2 + 1] = loc[j2]; --j2; }
                    loc[j2 + 1] = v;
                }
                for (int i2 = 0; i2 < n; ++i2) srt[lo + i2] = loc[i2];
            } else {            // overflow fallback (practically never)
                for (int i2 = lo + 1; i2 < hi; ++i2) {
                    unsigned long long v = srt[i2];
                    int j2 = i2 - 1;
                    while (j2 >= lo && srt[j2] > v) { srt[j2 + 1] = srt[j2]; --j2; }
                    srt[j2 + 1] = v;
                }
            }
        }
    }
    __syncthreads();

    // ================= Phase C: chunked greedy NMS over sorted list ========
    for (int pos = 0; pos < NPB; pos += CHK) {
        if (s_ncur >= TOPN) break;            // uniform (post-sync)
        int nc = s_ncur; (void)nc;

        // ---- load chunk candidates, bin by band ----
        if (t < CHK) {
            unsigned gidx = (unsigned)(srt[pos + t] & 0xFFFFu);
            float4 bx = boxes[gidx];
            float ab = __fmul_rn(__fsub_rn(bx.z, bx.x), __fsub_rn(bx.w, bx.y));
            s_cbox[t] = bx;
            s_carea[t] = ab;
            int bd = band_of(ab);
            s_cband[t] = (unsigned char)bd;
            atomicAdd(&s_bh[bd], 1);
            s_kill[t] = 0; s_kill[CHK + t] = 0;
        }
        __syncthreads();

        // scan 16 band bins -> band starts; reset s_bh for next chunk
        if (t < 32) {
            int v = (t < NBAND) ? s_bh[t] : 0;
            int x = v;
            #pragma unroll
            for (int o = 1; o < 32; o <<= 1) {
                int y = __shfl_up_sync(0xffffffffu, x, o);
                if (t >= o) x += y;
            }
            if (t < NBAND) { s_bstart[t] = x - v; s_bh[t] = 0; }
        }
        __syncthreads();
        if (t < CHK) {
            int q = atomicAdd(&s_bstart[s_cband[t]], 1);
            s_perm[q] = (unsigned short)t;
        }
        __syncthreads();

        // ---- prekill (band-coherent): grp parity splits each band list ----
        {
            int cand = (int)s_perm[p];
            float4 bx = s_cbox[cand];
            float  ab = s_carea[cand];
            float lo = __fmul_rn(ab, 0.49995f);
            float hi = __fmul_rn(ab, 2.0002f);
            bool kill = false;
            #pragma unroll 1
            for (int bd = 0; bd < NBAND && !kill; ++bd) {
                int cnt = s_bcnt[bd];
                if (cnt == 0) continue;
                if (s_bmax[bd] < lo || s_bmin[bd] > hi) continue;  // provably safe
                for (int k = grp; k < cnt && !kill; k += 2) {
                    int j = (int)s_bidx[bd][k];
                    kill = suppress_test(s_sel[j], s_sela[j], bx, ab);
                }
            }
            if (kill) s_kill[grp * CHK + cand] = 1;
        }
        __syncthreads();

        // ---- alive & order-preserving compaction ----
        bool alive = (grp == 0) && !(s_kill[p] | s_kill[CHK + p]);
        unsigned bal = __ballot_sync(0xffffffffu, alive);
        if (lane == 0) s_warp[wid] = __popc(bal);
        __syncthreads();
        if (t < 32) {
            unsigned wsum = s_warp[t], xx = wsum;
            #pragma unroll
            for (int o = 1; o < 32; o <<= 1) {
                unsigned y = __shfl_up_sync(0xffffffffu, xx, o);
                if (t >= o) xx += y;
            }
            s_warp[t] = xx - wsum;
            if (t == 31) s_M = (int)xx;
        }
        __syncthreads();
        if (alive) {
            int cpos = (int)s_warp[wid] + __popc(bal & ((1u << lane) - 1u));
            s_kbox[cpos] = s_cbox[p];
        }
        __syncthreads();
        int M = s_M;
        if (M == 0) continue;                 // uniform

        // zero only the mask rows we will use
        for (int i = t; i < M * 16; i += THREADS) s_mask[i] = 0;
        __syncthreads();

        // ---- pair enumeration among compacted survivors ----
        if (M >= 2 && p < M) {
            int half = M >> 1;
            float4 P = s_kbox[p];
            float pa = __fmul_rn(__fsub_rn(P.z, P.x), __fsub_rn(P.w, P.y));
            for (int d = 1 + grp; d <= half; d += 2) {
                int o = p + d; if (o >= M) o -= M;
                int a = p < o ? p : o;        // earlier = suppressor
                int c = p < o ? o : p;
                float4 C = s_kbox[o];
                float ca = __fmul_rn(__fsub_rn(C.z, C.x), __fsub_rn(C.w, C.y));
                if (suppress_test(P, pa, C, ca))
                    atomicOr(&s_mask[a * 16 + (c >> 5)], 1u << (c & 31));
            }
        }
        __syncthreads();

        // ---- warp0 greedy resolution over the bitmask + band append ----
        if (t < 32) {
            unsigned dead = 0;
            unsigned aliveW = 0;
            if (t < 16) {
                int base = t * 32;
                int rem = M - base;
                aliveW = (rem >= 32) ? 0xffffffffu
                       : (rem > 0 ? ((1u << rem) - 1u) : 0u);
            }
            int n = s_ncur;
            for (int w = 0; w < 16 && n < TOPN; ++w) {
                unsigned cur = __shfl_sync(0xffffffffu, aliveW & ~dead, w);
                while (cur && n < TOPN) {
                    int bitp = __ffs(cur) - 1;
                    int i = w * 32 + bitp;
                    cur &= cur - 1;
                    if (t == 0) {
                        float4 sb = s_kbox[i];
                        float sa = __fmul_rn(__fsub_rn(sb.z, sb.x),
                                             __fsub_rn(sb.w, sb.y));
                        s_sel[n] = sb;
                        s_sela[n] = sa;
                        int bd = band_of(sa);
                        int cc = s_bcnt[bd];
                        s_bidx[bd][cc] = (unsigned short)n;
                        s_bcnt[bd] = cc + 1;
                        s_bmin[bd] = fminf(s_bmin[bd], sa);
                        s_bmax[bd] = fmaxf(s_bmax[bd], sa);
                    }
                    n++;
                    unsigned row = (t < 16) ? s_mask[i * 16 + t] : 0u;
                    dead |= row;
                    unsigned rw = __shfl_sync(0xffffffffu, row, w);
                    cur &= ~rw;
                }
            }
            if (t == 0) s_ncur = n;
        }
        __syncthreads();
    }
    __syncthreads();
    const int nsel = s_ncur;

    // ================= Phase D: clip, select_rois, rank, emit ==============
    for (int j = t; j < TOPN; j += THREADS) {
        float4 bxo = make_float4(0.f, 0.f, 0.f, 0.f);
        if (j < nsel) {
            float4 vv = s_sel[j];
            bxo.x = fminf(fmaxf(vv.x, 0.f), 1.f);
            bxo.y = fminf(fmaxf(vv.y, 0.f), 1.f);
            bxo.z = fminf(fmaxf(vv.z, 0.f), 1.f);
            bxo.w = fminf(fmaxf(vv.w, 0.f), 1.f);
        }
        s_nms[j] = bxo;
    }
    for (int j = t; j < NGT; j += THREADS) {
        s_gt4[j] = ((const float4*)gt)[(size_t)b * NGT + j];
    }
    __syncthreads();

    if (t < TOPN) {
        float4 a = s_nms[t];
        float aa = __fmul_rn(__fsub_rn(a.z, a.x), __fsub_rn(a.w, a.y));
        float mg = -1.f; int bi = 0;
        #pragma unroll 4
        for (int g = 0; g < NGT; ++g) {
            float4 gb = s_gt4[g];
            float yy1 = fmaxf(a.x, gb.x);
            float xx1 = fmaxf(a.y, gb.y);
            float yy2 = fminf(a.z, gb.z);
            float xx2 = fminf(a.w, gb.w);
            float inter = __fmul_rn(fmaxf(__fsub_rn(yy2, yy1), 0.f),
                                    fmaxf(__fsub_rn(xx2, xx1), 0.f));
            float gba = __fmul_rn(__fsub_rn(gb.z, gb.x), __fsub_rn(gb.w, gb.y));
            float denom = __fadd_rn(__fsub_rn(__fadd_rn(aa, gba), inter), 1e-7f);
            float iou = __fdiv_rn(inter, denom);
            if (iou > mg) { mg = iou; bi = g; }
        }
        s_merged[t] = mg; s_gtbest[t] = bi;
    }
    __syncthreads();

    if (t < TOPN) {
        float mg = s_merged[t];
        int r = 0;
        for (int j = 0; j < TOPN; ++j) {
            float mj = s_merged[j];
            if (mj > mg || (mj == mg && j < t)) ++r;
        }
        if (r < TPOS) {
            float4 a = s_nms[t];
            float* roi = out + ((size_t)b * 128 + r) * 4;
            roi[0] = a.x; roi[1] = a.y; roi[2] = a.z; roi[3] = a.w;
            out[(size_t)BATCH * 128 * 4 + (size_t)b * TPOS + r] = (float)s_gtbest[t];
        }
    }
    for (int j = t; j < 64 * 4; j += THREADS) {
        out[((size_t)b * 128 + TPOS) * 4 + j] = 0.f;
    }
}

extern "C" void kernel_launch(void* const* d_in, const int* in_sizes, int n_in,
                              void* d_out, int out_size) {
    const float* deltas  = (const float*)d_in[0];
    const float* labels  = (const float*)d_in[1];
    const float* anchors = (const float*)d_in[2];
    const float* gt      = (const float*)d_in[3];
    float* out = (float*)d_out;
    cudaFuncSetAttribute(roi_kernel, cudaFuncAttributeMaxDynamicSharedMemorySize,
                         DYN_BYTES);
    roi_kernel<<<BATCH, THREADS, DYN_BYTES>>>(deltas, labels, anchors, gt, out);
}

// round 10
// speedup vs baseline: 1.1210x; 1.1210x over previous
#include <cuda_runtime.h>
#include <math.h>

#define BATCH   16
#define NPB     36864      // boxes per batch = 64*64*9
#define THREADS 1024
#define PER_TH  36         // NPB / THREADS
#define TOPN    300
#define NGT     64
#define TPOS    64
#define NBUCK   4096
#define CHK     512        // NMS chunk size

// L2-resident scratch (no cudaMalloc allowed)
__device__ float4             g_boxes[BATCH * NPB];
__device__ unsigned long long g_tmp[BATCH * NPB];     // bucketed (unsorted within)
__device__ unsigned long long g_sorted[BATCH * NPB];  // fully sorted

// dynamic smem layout (u32 units)
#define OFF_CUM   4096       // u32[4097] (+pad)
#define OFF_BPOS  8200       // u32[4096]
#define OFF_KBOX  12296      // float4[512]
#define OFF_MASK  14344      // u32[512*16]
#define DYN_U32   22536
#define DYN_BYTES (DYN_U32 * 4)

// bucket from descending key30 (monotone coarsening): uniform in score VALUE.
__device__ __forceinline__ unsigned bucket_of(unsigned key30) {
    float s = __uint_as_float(0x3F7FFFFFu - key30);
    unsigned q = (unsigned)__fmul_rn(s, 4096.f);
    if (q > 4095u) q = 4095u;
    return 4095u - q;
}

// Mostly-branchless suppression test: guard band + exact division fallback.
__device__ __forceinline__ bool suppress_test(float4 sb, float sa, float4 bx, float ab) {
    float yy1 = fmaxf(sb.x, bx.x);
    float xx1 = fmaxf(sb.y, bx.y);
    float yy2 = fminf(sb.z, bx.z);
    float xx2 = fminf(sb.w, bx.w);
    float ih  = fmaxf(__fsub_rn(yy2, yy1), 0.f);
    float iw  = fmaxf(__fsub_rn(xx2, xx1), 0.f);
    float inter = __fmul_rn(ih, iw);
    float denom = __fadd_rn(__fsub_rn(__fadd_rn(sa, ab), inter), 1e-7f);
    float e = __fmaf_rn(-0.5f, denom, inter);
    float margin = __fmul_rn(denom, 1e-4f);
    bool sup = e > margin;
    if (fabsf(e) <= margin)                        // rare: exact reference path
        sup = __fdiv_rn(inter, denom) >= 0.5f;
    return sup;
}

__global__ void __launch_bounds__(THREADS, 1)
roi_kernel(const float* __restrict__ deltas,
           const float* __restrict__ labels,
           const float* __restrict__ anchors,
           const float* __restrict__ gt,
           float* __restrict__ out)
{
    extern __shared__ unsigned s_dyn[];
    unsigned* s_hist = s_dyn;
    unsigned* s_cum  = s_dyn + OFF_CUM;              // 4097 entries
    unsigned* s_bpos = s_dyn + OFF_BPOS;
    float4*   s_kbox = (float4*)(s_dyn + OFF_KBOX);  // 512 compacted boxes
    unsigned* s_mask = s_dyn + OFF_MASK;             // 512 rows x 16 words

    __shared__ float4 s_sel[TOPN];
    __shared__ float  s_sela[TOPN];
    __shared__ float4 s_nms[TOPN];
    __shared__ float  s_merged[TOPN];
    __shared__ int    s_gtbest[TOPN];
    __shared__ float4 s_gt4[NGT];
    __shared__ unsigned s_warp[32];
    __shared__ unsigned s_kalA[16], s_kalB[16];
    __shared__ int    s_ncur, s_M;

    const int b = blockIdx.x;
    const int t = threadIdx.x;
    const int lane = t & 31, wid = t >> 5;
    const int p    = t & (CHK - 1);   // candidate slot within chunk
    const int grp  = t >> 9;          // 0 or 1

    const float4* anc4 = (const float4*)(anchors) + (size_t)b * NPB;
    const float4* dlt4 = (const float4*)(deltas)  + (size_t)b * NPB;
    const float*  lab  = labels + (size_t)b * NPB;
    float4*             boxes = g_boxes  + (size_t)b * NPB;
    unsigned long long* tmp   = g_tmp    + (size_t)b * NPB;
    unsigned long long* srt   = g_sorted + (size_t)b * NPB;

    // ================= Phase A: decode + bucket histogram ==================
    #pragma unroll
    for (int c = 0; c < 4; ++c) s_hist[c * 1024 + t] = 0;
    if (t == 0) s_ncur = 0;
    __syncthreads();

    #pragma unroll 4
    for (int k = 0; k < PER_TH; ++k) {
        int i = t + k * THREADS;
        float4 a = anc4[i];
        float4 d = dlt4[i];
        float ah  = __fsub_rn(a.z, a.x);
        float aw  = __fsub_rn(a.w, a.y);
        float acy = __fadd_rn(a.x, __fmul_rn(0.5f, ah));
        float acx = __fadd_rn(a.y, __fmul_rn(0.5f, aw));
        float h   = __fmul_rn(expf(d.z), ah);
        float w   = __fmul_rn(expf(d.w), aw);
        float cy  = __fadd_rn(__fmul_rn(d.x, ah), acy);
        float cx  = __fadd_rn(__fmul_rn(d.y, aw), acx);
        float y1  = __fsub_rn(cy, __fmul_rn(0.5f, h));
        float x1  = __fsub_rn(cx, __fmul_rn(0.5f, w));
        boxes[i]  = make_float4(y1, x1, __fadd_rn(y1, h), __fadd_rn(x1, w));
        unsigned key30 = 0x3F7FFFFFu - __float_as_uint(lab[i]);
        atomicAdd(&s_hist[bucket_of(key30)], 1u);
    }
    __syncthreads();

    // ================= Phase B: exclusive scan -> cum; bpos = cum ==========
    {
        unsigned v[4], sum = 0;
        #pragma unroll
        for (int j = 0; j < 4; ++j) { v[j] = s_hist[t * 4 + j]; }
        unsigned e[4];
        #pragma unroll
        for (int j = 0; j < 4; ++j) { e[j] = sum; sum += v[j]; }
        unsigned x = sum;
        #pragma unroll
        for (int o = 1; o < 32; o <<= 1) {
            unsigned y = __shfl_up_sync(0xffffffffu, x, o);
            if (lane >= o) x += y;
        }
        if (lane == 31) s_warp[wid] = x;
        __syncthreads();
        if (t < 32) {
            unsigned wsum = s_warp[t], xx = wsum;
            #pragma unroll
            for (int o = 1; o < 32; o <<= 1) {
                unsigned y = __shfl_up_sync(0xffffffffu, xx, o);
                if (t >= o) xx += y;
            }
            s_warp[t] = xx - wsum;
        }
        __syncthreads();
        unsigned prefix = s_warp[wid] + (x - sum);
        #pragma unroll
        for (int j = 0; j < 4; ++j) {
            s_cum[t * 4 + j]  = prefix + e[j];
            s_bpos[t * 4 + j] = prefix + e[j];
        }
        if (t == THREADS - 1) s_cum[NBUCK] = prefix + sum;
        __syncthreads();
    }

    // ========= Phase A2: counting-sort scatter into g_tmp ==================
    #pragma unroll 4
    for (int k = 0; k < PER_TH; ++k) {
        int i = t + k * THREADS;
        unsigned key30 = 0x3F7FFFFFu - __float_as_uint(lab[i]);
        unsigned bk = bucket_of(key30);
        unsigned slot = atomicAdd(&s_bpos[bk], 1u);
        tmp[slot] = ((unsigned long long)key30 << 16) | (unsigned)i;
    }
    __syncthreads();

    // ========= Phase B2: per-bucket rank sort (independent reads, no chain) =
    // keys unique (idx in low bits) => ranks unique => exact permutation.
    #pragma unroll
    for (int c = 0; c < 4; ++c) {
        int bk = t + c * THREADS;
        int lo = (int)s_cum[bk], hi = (int)s_cum[bk + 1];
        for (int i2 = lo; i2 < hi; ++i2) {
            unsigned long long v = tmp[i2];
            int r = 0;
            for (int j2 = lo; j2 < hi; ++j2) r += (tmp[j2] < v);
            srt[lo + r] = v;
        }
    }
    __syncthreads();

    // ================= Phase C: chunked greedy NMS over sorted list ========
    for (int pos = 0; pos < NPB; pos += CHK) {
        if (s_ncur >= TOPN) break;            // uniform (post-sync)
        int nc = s_ncur;

        // ---- load candidate (both groups hold the same box) ----
        unsigned gidx = (unsigned)(srt[pos + p] & 0xFFFFu);
        float4 bx = boxes[gidx];
        float  ab = __fmul_rn(__fsub_rn(bx.z, bx.x), __fsub_rn(bx.w, bx.y));

        // ---- split prekill with batched early-exit (pipelined loads) ----
        int ncA = (nc + 1) >> 1;
        int j0 = grp ? ncA : 0;
        int j1 = grp ? nc  : ncA;
        bool kill = false;
        int j = j0;
        while (j + 8 <= j1 && !kill) {
            bool k2 = false;
            #pragma unroll
            for (int q = 0; q < 8; ++q)
                k2 |= suppress_test(s_sel[j + q], s_sela[j + q], bx, ab);
            kill = k2;
            j += 8;
        }
        if (!kill) {
            bool k2 = false;
            for (; j < j1; ++j)
                k2 |= suppress_test(s_sel[j], s_sela[j], bx, ab);
            kill = k2;
        }
        unsigned kb = __ballot_sync(0xffffffffu, kill);
        if (lane == 0) { if (grp == 0) s_kalA[wid] = kb; else s_kalB[wid - 16] = kb; }
        __syncthreads();

        // ---- merge kill info, compact alive (order-preserving) ----
        bool alive = false;
        if (grp == 0) {
            unsigned kw = s_kalA[p >> 5] | s_kalB[p >> 5];
            alive = !((kw >> (p & 31)) & 1u);
        }
        unsigned bal = __ballot_sync(0xffffffffu, alive);
        if (lane == 0) s_warp[wid] = __popc(bal);
        __syncthreads();
        if (t < 32) {
            unsigned wsum = s_warp[t], xx = wsum;
            #pragma unroll
            for (int o = 1; o < 32; o <<= 1) {
                unsigned y = __shfl_up_sync(0xffffffffu, xx, o);
                if (t >= o) xx += y;
            }
            s_warp[t] = xx - wsum;
            if (t == 31) s_M = (int)xx;
        }
        __syncthreads();
        int M = s_M;
        if (alive) {
            int cpos = (int)s_warp[wid] + __popc(bal & ((1u << lane) - 1u));
            s_kbox[cpos] = bx;
        }
        // zero only the mask rows we will use
        for (int i = t; i < M * 16; i += THREADS) s_mask[i] = 0;
        __syncthreads();
        if (M == 0) continue;                 // uniform

        // ---- pair enumeration among compacted survivors ----
        if (M >= 2 && p < M) {
            int half = M >> 1;
            float4 P = s_kbox[p];
            float pa = __fmul_rn(__fsub_rn(P.z, P.x), __fsub_rn(P.w, P.y));
            for (int d = 1 + grp; d <= half; d += 2) {
                int o = p + d; if (o >= M) o -= M;
                int a = p < o ? p : o;        // earlier = suppressor
                int c = p < o ? o : p;
                float4 C = s_kbox[o];
                float ca = __fmul_rn(__fsub_rn(C.z, C.x), __fsub_rn(C.w, C.y));
                if (suppress_test(P, pa, C, ca))
                    atomicOr(&s_mask[a * 16 + (c >> 5)], 1u << (c & 31));
            }
        }
        __syncthreads();

        // ---- warp0 greedy resolution over the bitmask (no block BARs) ----
        if (t < 32) {
            unsigned dead = 0;
            unsigned aliveW = 0;
            if (t < 16) {
                int base = t * 32;
                int rem = M - base;
                aliveW = (rem >= 32) ? 0xffffffffu
                       : (rem > 0 ? ((1u << rem) - 1u) : 0u);
            }
            int n = nc;
            for (int w = 0; w < 16 && n < TOPN; ++w) {
                unsigned cur = __shfl_sync(0xffffffffu, aliveW & ~dead, w);
                while (cur && n < TOPN) {
                    int bitp = __ffs(cur) - 1;
                    int i = w * 32 + bitp;
                    cur &= cur - 1;
                    if (t == 0) {
                        float4 sb = s_kbox[i];
                        s_sel[n] = sb;
                        s_sela[n] = __fmul_rn(__fsub_rn(sb.z, sb.x),
                                              __fsub_rn(sb.w, sb.y));
                    }
                    n++;
                    unsigned row = (t < 16) ? s_mask[i * 16 + t] : 0u;
                    dead |= row;
                    unsigned rw = __shfl_sync(0xffffffffu, row, w);
                    cur &= ~rw;
                }
            }
            if (t == 0) s_ncur = n;
        }
        __syncthreads();
    }
    __syncthreads();
    const int nsel = s_ncur;

    // ================= Phase D: clip, select_rois, rank, emit ==============
    for (int j = t; j < TOPN; j += THREADS) {
        float4 bxo = make_float4(0.f, 0.f, 0.f, 0.f);
        if (j < nsel) {
            float4 vv = s_sel[j];
            bxo.x = fminf(fmaxf(vv.x, 0.f), 1.f);
            bxo.y = fminf(fmaxf(vv.y, 0.f), 1.f);
            bxo.z = fminf(fmaxf(vv.z, 0.f), 1.f);
            bxo.w = fminf(fmaxf(vv.w, 0.f), 1.f);
        }
        s_nms[j] = bxo;
    }
    for (int j = t; j < NGT; j += THREADS) {
        s_gt4[j] = ((const float4*)gt)[(size_t)b * NGT + j];
    }
    __syncthreads();

    if (t < TOPN) {
        float4 a = s_nms[t];
        float aa = __fmul_rn(__fsub_rn(a.z, a.x), __fsub_rn(a.w, a.y));
        float mg = -1.f; int bi = 0;
        #pragma unroll 4
        for (int g = 0; g < NGT; ++g) {
            float4 gb = s_gt4[g];
            float yy1 = fmaxf(a.x, gb.x);
            float xx1 = fmaxf(a.y, gb.y);
            float yy2 = fminf(a.z, gb.z);
            float xx2 = fminf(a.w, gb.w);
            float inter = __fmul_rn(fmaxf(__fsub_rn(yy2, yy1), 0.f),
                                    fmaxf(__fsub_rn(xx2, xx1), 0.f));
            float gba = __fmul_rn(__fsub_rn(gb.z, gb.x), __fsub_rn(gb.w, gb.y));
            float denom = __fadd_rn(__fsub_rn(__fadd_rn(aa, gba), inter), 1e-7f);
            float iou = __fdiv_rn(inter, denom);
            if (iou > mg) { mg = iou; bi = g; }
        }
        s_merged[t] = mg; s_gtbest[t] = bi;
    }
    __syncthreads();

    if (t < TOPN) {
        float mg = s_merged[t];
        int r = 0;
        for (int j = 0; j < TOPN; ++j) {
            float mj = s_merged[j];
            if (mj > mg || (mj == mg && j < t)) ++r;
        }
        if (r < TPOS) {
            float4 a = s_nms[t];
            float* roi = out + ((size_t)b * 128 + r) * 4;
            roi[0] = a.x; roi[1] = a.y; roi[2] = a.z; roi[3] = a.w;
            out[(size_t)BATCH * 128 * 4 + (size_t)b * TPOS + r] = (float)s_gtbest[t];
        }
    }
    for (int j = t; j < 64 * 4; j += THREADS) {
        out[((size_t)b * 128 + TPOS) * 4 + j] = 0.f;
    }
}

extern "C" void kernel_launch(void* const* d_in, const int* in_sizes, int n_in,
                              void* d_out, int out_size) {
    const float* deltas  = (const float*)d_in[0];
    const float* labels  = (const float*)d_in[1];
    const float* anchors = (const float*)d_in[2];
    const float* gt      = (const float*)d_in[3];
    float* out = (float*)d_out;
    cudaFuncSetAttribute(roi_kernel, cudaFuncAttributeMaxDynamicSharedMemorySize,
                         DYN_BYTES);
    roi_kernel<<<BATCH, THREADS, DYN_BYTES>>>(deltas, labels, anchors, gt, out);
}

// round 12
// speedup vs baseline: 1.1410x; 1.0178x over previous
#include <cuda_runtime.h>
#include <math.h>

#define BATCH   16
#define NPB     36864      // boxes per batch = 64*64*9
#define THREADS 1024
#define PER_TH  36         // NPB / THREADS
#define TOPN    300
#define NGT     64
#define TPOS    64
#define NBUCK   4096
#define CHK     512        // NMS chunk size

// L2-resident scratch (no cudaMalloc allowed)
__device__ float4             g_boxes[BATCH * NPB];
__device__ unsigned long long g_tmp[BATCH * NPB];     // bucketed (unsorted within)
__device__ unsigned long long g_sorted[BATCH * NPB];  // fully sorted

// dynamic smem layout (u32 units)
#define OFF_CUM   4096       // u32[4097] (+pad)
#define OFF_BPOS  8200       // u32[4096]
#define OFF_KBOX  12296      // float4[512]
#define OFF_MASK  14344      // u32[512*16]
#define DYN_U32   22536
#define DYN_BYTES (DYN_U32 * 4)

// bucket from descending key30 (monotone coarsening): uniform in score VALUE.
__device__ __forceinline__ unsigned bucket_of(unsigned key30) {
    float s = __uint_as_float(0x3F7FFFFFu - key30);
    unsigned q = (unsigned)__fmul_rn(s, 4096.f);
    if (q > 4095u) q = 4095u;
    return 4095u - q;
}

// Exact-threshold suppression test (BRANCHY: division only behind a real branch).
__device__ __forceinline__ bool suppress_test(float4 sb, float sa, float4 bx, float ab) {
    float yy1 = fmaxf(sb.x, bx.x);
    float xx1 = fmaxf(sb.y, bx.y);
    float yy2 = fminf(sb.z, bx.z);
    float xx2 = fminf(sb.w, bx.w);
    float ih  = fmaxf(__fsub_rn(yy2, yy1), 0.f);
    float iw  = fmaxf(__fsub_rn(xx2, xx1), 0.f);
    float inter = __fmul_rn(ih, iw);
    float denom = __fadd_rn(__fsub_rn(__fadd_rn(sa, ab), inter), 1e-7f);
    float e = __fmaf_rn(-0.5f, denom, inter);
    float margin = __fmul_rn(denom, 1e-4f);
    if (e < -margin) return false;
    if (e >  margin) return true;
    return __fdiv_rn(inter, denom) >= 0.5f;       // exact reference semantics
}

// Division-free (e, margin) for the batched fast path. Pure FMA/min/max.
__device__ __forceinline__ void pair_em(float4 sb, float sa, float4 bx, float ab,
                                        float& e, float& m) {
    float yy1 = fmaxf(sb.x, bx.x);
    float xx1 = fmaxf(sb.y, bx.y);
    float yy2 = fminf(sb.z, bx.z);
    float xx2 = fminf(sb.w, bx.w);
    float ih  = fmaxf(__fsub_rn(yy2, yy1), 0.f);
    float iw  = fmaxf(__fsub_rn(xx2, xx1), 0.f);
    float inter = __fmul_rn(ih, iw);
    float denom = __fadd_rn(__fsub_rn(__fadd_rn(sa, ab), inter), 1e-7f);
    e = __fmaf_rn(-0.5f, denom, inter);
    m = __fmul_rn(denom, 1e-4f);
}

__global__ void __launch_bounds__(THREADS, 1)
roi_kernel(const float* __restrict__ deltas,
           const float* __restrict__ labels,
           const float* __restrict__ anchors,
           const float* __restrict__ gt,
           float* __restrict__ out)
{
    extern __shared__ unsigned s_dyn[];
    unsigned* s_hist = s_dyn;
    unsigned* s_cum  = s_dyn + OFF_CUM;              // 4097 entries
    unsigned* s_bpos = s_dyn + OFF_BPOS;
    float4*   s_kbox = (float4*)(s_dyn + OFF_KBOX);  // 512 compacted boxes
    unsigned* s_mask = s_dyn + OFF_MASK;             // 512 rows x 16 words

    __shared__ float4 s_sel[TOPN];
    __shared__ float  s_sela[TOPN];
    __shared__ float4 s_nms[TOPN];
    __shared__ float  s_merged[TOPN];
    __shared__ int    s_gtbest[TOPN];
    __shared__ float4 s_gt4[NGT];
    __shared__ unsigned s_warp[32];
    __shared__ unsigned s_kalA[16], s_kalB[16];
    __shared__ int    s_ncur, s_M;

    const int b = blockIdx.x;
    const int t = threadIdx.x;
    const int lane = t & 31, wid = t >> 5;
    const int p    = t & (CHK - 1);   // candidate slot within chunk
    const int grp  = t >> 9;          // 0 or 1

    const float4* anc4 = (const float4*)(anchors) + (size_t)b * NPB;
    const float4* dlt4 = (const float4*)(deltas)  + (size_t)b * NPB;
    const float*  lab  = labels + (size_t)b * NPB;
    float4*             boxes = g_boxes  + (size_t)b * NPB;
    unsigned long long* tmp   = g_tmp    + (size_t)b * NPB;
    unsigned long long* srt   = g_sorted + (size_t)b * NPB;

    // ================= Phase A: decode + bucket histogram ==================
    #pragma unroll
    for (int c = 0; c < 4; ++c) s_hist[c * 1024 + t] = 0;
    if (t == 0) s_ncur = 0;
    __syncthreads();

    #pragma unroll 4
    for (int k = 0; k < PER_TH; ++k) {
        int i = t + k * THREADS;
        float4 a = anc4[i];
        float4 d = dlt4[i];
        float ah  = __fsub_rn(a.z, a.x);
        float aw  = __fsub_rn(a.w, a.y);
        float acy = __fadd_rn(a.x, __fmul_rn(0.5f, ah));
        float acx = __fadd_rn(a.y, __fmul_rn(0.5f, aw));
        float h   = __fmul_rn(expf(d.z), ah);
        float w   = __fmul_rn(expf(d.w), aw);
        float cy  = __fadd_rn(__fmul_rn(d.x, ah), acy);
        float cx  = __fadd_rn(__fmul_rn(d.y, aw), acx);
        float y1  = __fsub_rn(cy, __fmul_rn(0.5f, h));
        float x1  = __fsub_rn(cx, __fmul_rn(0.5f, w));
        boxes[i]  = make_float4(y1, x1, __fadd_rn(y1, h), __fadd_rn(x1, w));
        unsigned key30 = 0x3F7FFFFFu - __float_as_uint(lab[i]);
        atomicAdd(&s_hist[bucket_of(key30)], 1u);
    }
    __syncthreads();

    // ================= Phase B: exclusive scan -> cum; bpos = cum ==========
    {
        unsigned v[4], sum = 0;
        #pragma unroll
        for (int j = 0; j < 4; ++j) { v[j] = s_hist[t * 4 + j]; }
        unsigned e[4];
        #pragma unroll
        for (int j = 0; j < 4; ++j) { e[j] = sum; sum += v[j]; }
        unsigned x = sum;
        #pragma unroll
        for (int o = 1; o < 32; o <<= 1) {
            unsigned y = __shfl_up_sync(0xffffffffu, x, o);
            if (lane >= o) x += y;
        }
        if (lane == 31) s_warp[wid] = x;
        __syncthreads();
        if (t < 32) {
            unsigned wsum = s_warp[t], xx = wsum;
            #pragma unroll
            for (int o = 1; o < 32; o <<= 1) {
                unsigned y = __shfl_up_sync(0xffffffffu, xx, o);
                if (t >= o) xx += y;
            }
            s_warp[t] = xx - wsum;
        }
        __syncthreads();
        unsigned prefix = s_warp[wid] + (x - sum);
        #pragma unroll
        for (int j = 0; j < 4; ++j) {
            s_cum[t * 4 + j]  = prefix + e[j];
            s_bpos[t * 4 + j] = prefix + e[j];
        }
        if (t == THREADS - 1) s_cum[NBUCK] = prefix + sum;
        __syncthreads();
    }

    // ========= Phase A2: counting-sort scatter into g_tmp ==================
    #pragma unroll 4
    for (int k = 0; k < PER_TH; ++k) {
        int i = t + k * THREADS;
        unsigned key30 = 0x3F7FFFFFu - __float_as_uint(lab[i]);
        unsigned bk = bucket_of(key30);
        unsigned slot = atomicAdd(&s_bpos[bk], 1u);
        tmp[slot] = ((unsigned long long)key30 << 16) | (unsigned)i;
    }
    __syncthreads();

    // ========= Phase B2: per-bucket rank sort (independent reads, no chain) =
    #pragma unroll
    for (int c = 0; c < 4; ++c) {
        int bk = t + c * THREADS;
        int lo = (int)s_cum[bk], hi = (int)s_cum[bk + 1];
        for (int i2 = lo; i2 < hi; ++i2) {
            unsigned long long v = tmp[i2];
            int r = 0;
            for (int j2 = lo; j2 < hi; ++j2) r += (tmp[j2] < v);
            srt[lo + r] = v;
        }
    }
    __syncthreads();

    // ================= Phase C: chunked greedy NMS over sorted list ========
    for (int pos = 0; pos < NPB; pos += CHK) {
        if (s_ncur >= TOPN) break;            // uniform (post-sync)
        int nc = s_ncur;

        // ---- load candidate (both groups hold the same box) ----
        unsigned gidx = (unsigned)(srt[pos + p] & 0xFFFFu);
        float4 bx = boxes[gidx];
        float  ab = __fmul_rn(__fsub_rn(bx.z, bx.x), __fsub_rn(bx.w, bx.y));

        // ---- split prekill: 8-wide division-free batches, exit between ----
        int ncA = (nc + 1) >> 1;
        int j0 = grp ? ncA : 0;
        int j1 = grp ? nc  : ncA;
        bool kill = false;
        int j = j0;
        while (j + 8 <= j1 && !kill) {
            bool k8 = false, u8 = false;
            #pragma unroll
            for (int q = 0; q < 8; ++q) {
                float e, m;
                pair_em(s_sel[j + q], s_sela[j + q], bx, ab, e, m);
                k8 |= (e > m);
                u8 |= (fabsf(e) <= m);
            }
            if (k8) {
                kill = true;                  // definite kill: exact by guard band
            } else if (u8) {                  // rare: resolve exactly
                for (int q = 0; q < 8 && !kill; ++q)
                    kill = suppress_test(s_sel[j + q], s_sela[j + q], bx, ab);
            }
            j += 8;
        }
        while (j < j1 && !kill) {             // tail
            kill = suppress_test(s_sel[j], s_sela[j], bx, ab);
            ++j;
        }
        unsigned kb = __ballot_sync(0xffffffffu, kill);
        if (lane == 0) { if (grp == 0) s_kalA[wid] = kb; else s_kalB[wid - 16] = kb; }
        __syncthreads();

        // ---- merge kill info, compact alive (order-preserving) ----
        bool alive = false;
        if (grp == 0) {
            unsigned kw = s_kalA[p >> 5] | s_kalB[p >> 5];
            alive = !((kw >> (p & 31)) & 1u);
        }
        unsigned bal = __ballot_sync(0xffffffffu, alive);
        if (lane == 0) s_warp[wid] = __popc(bal);
        __syncthreads();
        if (t < 32) {
            unsigned wsum = s_warp[t], xx = wsum;
            #pragma unroll
            for (int o = 1; o < 32; o <<= 1) {
                unsigned y = __shfl_up_sync(0xffffffffu, xx, o);
                if (t >= o) xx += y;
            }
            s_warp[t] = xx - wsum;
            if (t == 31) s_M = (int)xx;
        }
        __syncthreads();
        int M = s_M;
        if (alive) {
            int cpos = (int)s_warp[wid] + __popc(bal & ((1u << lane) - 1u));
            s_kbox[cpos] = bx;
        }
        // zero only the mask rows we will use
        for (int i = t; i < M * 16; i += THREADS) s_mask[i] = 0;
        __syncthreads();
        if (M == 0) continue;                 // uniform

        // ---- pair enumeration among compacted survivors ----
        if (M >= 2 && p < M) {
            int half = M >> 1;
            float4 P = s_kbox[p];
            float pa = __fmul_rn(__fsub_rn(P.z, P.x), __fsub_rn(P.w, P.y));
            for (int d = 1 + grp; d <= half; d += 2) {
                int o = p + d; if (o >= M) o -= M;
                int a = p < o ? p : o;        // earlier = suppressor
                int c = p < o ? o : p;
                float4 C = s_kbox[o];
                float ca = __fmul_rn(__fsub_rn(C.z, C.x), __fsub_rn(C.w, C.y));
                if (suppress_test(P, pa, C, ca))
                    atomicOr(&s_mask[a * 16 + (c >> 5)], 1u << (c & 31));
            }
        }
        __syncthreads();

        // ---- warp0 greedy resolution over the bitmask (no block BARs) ----
        if (t < 32) {
            unsigned dead = 0;
            unsigned aliveW = 0;
            if (t < 16) {
                int base = t * 32;
                int rem = M - base;
                aliveW = (rem >= 32) ? 0xffffffffu
                       : (rem > 0 ? ((1u << rem) - 1u) : 0u);
            }
            int n = nc;
            for (int w = 0; w < 16 && n < TOPN; ++w) {
                unsigned cur = __shfl_sync(0xffffffffu, aliveW & ~dead, w);
                while (cur && n < TOPN) {
                    int bitp = __ffs(cur) - 1;
                    int i = w * 32 + bitp;
                    cur &= cur - 1;
                    if (t == 0) {
                        float4 sb = s_kbox[i];
                        s_sel[n] = sb;
                        s_sela[n] = __fmul_rn(__fsub_rn(sb.z, sb.x),
                                              __fsub_rn(sb.w, sb.y));
                    }
                    n++;
                    unsigned row = (t < 16) ? s_mask[i * 16 + t] : 0u;
                    dead |= row;
                    unsigned rw = __shfl_sync(0xffffffffu, row, w);
                    cur &= ~rw;
                }
            }
            if (t == 0) s_ncur = n;
        }
        __syncthreads();
    }
    __syncthreads();
    const int nsel = s_ncur;

    // ================= Phase D: clip, select_rois, rank, emit ==============
    for (int j = t; j < TOPN; j += THREADS) {
        float4 bxo = make_float4(0.f, 0.f, 0.f, 0.f);
        if (j < nsel) {
            float4 vv = s_sel[j];
            bxo.x = fminf(fmaxf(vv.x, 0.f), 1.f);
            bxo.y = fminf(fmaxf(vv.y, 0.f), 1.f);
            bxo.z = fminf(fmaxf(vv.z, 0.f), 1.f);
            bxo.w = fminf(fmaxf(vv.w, 0.f), 1.f);
        }
        s_nms[j] = bxo;
    }
    for (int j = t; j < NGT; j += THREADS) {
        s_gt4[j] = ((const float4*)gt)[(size_t)b * NGT + j];
    }
    __syncthreads();

    if (t < TOPN) {
        float4 a = s_nms[t];
        float aa = __fmul_rn(__fsub_rn(a.z, a.x), __fsub_rn(a.w, a.y));
        float mg = -1.f; int bi = 0;
        #pragma unroll 4
        for (int g = 0; g < NGT; ++g) {
            float4 gb = s_gt4[g];
            float yy1 = fmaxf(a.x, gb.x);
            float xx1 = fmaxf(a.y, gb.y);
            float yy2 = fminf(a.z, gb.z);
            float xx2 = fminf(a.w, gb.w);
            float inter = __fmul_rn(fmaxf(__fsub_rn(yy2, yy1), 0.f),
                                    fmaxf(__fsub_rn(xx2, xx1), 0.f));
            float gba = __fmul_rn(__fsub_rn(gb.z, gb.x), __fsub_rn(gb.w, gb.y));
            float denom = __fadd_rn(__fsub_rn(__fadd_rn(aa, gba), inter), 1e-7f);
            float iou = __fdiv_rn(inter, denom);
            if (iou > mg) { mg = iou; bi = g; }
        }
        s_merged[t] = mg; s_gtbest[t] = bi;
    }
    __syncthreads();

    if (t < TOPN) {
        float mg = s_merged[t];
        int r = 0;
        for (int j = 0; j < TOPN; ++j) {
            float mj = s_merged[j];
            if (mj > mg || (mj == mg && j < t)) ++r;
        }
        if (r < TPOS) {
            float4 a = s_nms[t];
            float* roi = out + ((size_t)b * 128 + r) * 4;
            roi[0] = a.x; roi[1] = a.y; roi[2] = a.z; roi[3] = a.w;
            out[(size_t)BATCH * 128 * 4 + (size_t)b * TPOS + r] = (float)s_gtbest[t];
        }
    }
    for (int j = t; j < 64 * 4; j += THREADS) {
        out[((size_t)b * 128 + TPOS) * 4 + j] = 0.f;
    }
}

extern "C" void kernel_launch(void* const* d_in, const int* in_sizes, int n_in,
                              void* d_out, int out_size) {
    const float* deltas  = (const float*)d_in[0];
    const float* labels  = (const float*)d_in[1];
    const float* anchors = (const float*)d_in[2];
    const float* gt      = (const float*)d_in[3];
    float* out = (float*)d_out;
    cudaFuncSetAttribute(roi_kernel, cudaFuncAttributeMaxDynamicSharedMemorySize,
                         DYN_BYTES);
    roi_kernel<<<BATCH, THREADS, DYN_BYTES>>>(deltas, labels, anchors, gt, out);
}

// round 13
// speedup vs baseline: 1.6820x; 1.4742x over previous
#include <cuda_runtime.h>
#include <math.h>

#define BATCH   16
#define NPB     36864      // boxes per batch = 64*64*9
#define THREADS 1024
#define PER_TH  36         // NPB / THREADS
#define TOPN    300
#define NGT     64
#define TPOS    64
#define NBUCK   4096
#define SLABSZ  7936u
#define NSLAB   5          // ceil(36864/7936)
#define PPOW    8192       // slab capacity
#define CHK     512        // NMS chunk size

// L2-resident scratch (no cudaMalloc allowed)
__device__ float4   g_boxes[BATCH * NPB];
__device__ unsigned g_k30[BATCH * NPB];

// dynamic smem layout (u32 units):
//  [0, 16384)        s_key u64[8192]   (aliased by s_hist u32[4096] in phase A)
//  [16384, 20481)    s_cum u32[4097]  (+pad to 20484)
//  [20484, 24580)    s_bpos u32[4096]
//  [24580, 26628)    s_kbox float4[512]
//  [26628, 34820)    s_mask u32[512*16]
#define OFF_CUM   16384
#define OFF_BPOS  20484
#define OFF_KBOX  24580
#define OFF_MASK  26628
#define DYN_U32   34820
#define DYN_BYTES (DYN_U32 * 4)

// bucket from descending key30 (monotone coarsening): uniform in score VALUE.
__device__ __forceinline__ unsigned bucket_of(unsigned key30) {
    float s = __uint_as_float(0x3F7FFFFFu - key30);
    unsigned q = (unsigned)__fmul_rn(s, 4096.f);
    if (q > 4095u) q = 4095u;
    return 4095u - q;
}

// Exact-threshold suppression test: guard band + exact division fallback.
__device__ __forceinline__ bool suppress_test(float4 sb, float sa, float4 bx, float ab) {
    float yy1 = fmaxf(sb.x, bx.x);
    float xx1 = fmaxf(sb.y, bx.y);
    float yy2 = fminf(sb.z, bx.z);
    float xx2 = fminf(sb.w, bx.w);
    float ih  = fmaxf(__fsub_rn(yy2, yy1), 0.f);
    float iw  = fmaxf(__fsub_rn(xx2, xx1), 0.f);
    float inter = __fmul_rn(ih, iw);
    float denom = __fadd_rn(__fsub_rn(__fadd_rn(sa, ab), inter), 1e-7f);
    float e = __fmaf_rn(-0.5f, denom, inter);
    float margin = __fmul_rn(denom, 1e-4f);
    if (e < -margin) return false;
    if (e >  margin) return true;
    return __fdiv_rn(inter, denom) >= 0.5f;       // exact reference semantics
}

__global__ void __launch_bounds__(THREADS, 1)
roi_kernel(const float* __restrict__ deltas,
           const float* __restrict__ labels,
           const float* __restrict__ anchors,
           const float* __restrict__ gt,
           float* __restrict__ out)
{
    extern __shared__ unsigned s_dyn[];
    unsigned long long* s_key = (unsigned long long*)s_dyn;
    unsigned* s_hist = s_dyn;                        // alias (phase A only)
    unsigned* s_cum  = s_dyn + OFF_CUM;              // 4097 entries
    unsigned* s_bpos = s_dyn + OFF_BPOS;             // per-slab bucket counters
    float4*   s_kbox = (float4*)(s_dyn + OFF_KBOX);  // 512 compacted boxes
    unsigned* s_mask = s_dyn + OFF_MASK;             // 512 rows x 16 words

    __shared__ float4 s_sel[TOPN];
    __shared__ float  s_sela[TOPN];
    __shared__ float4 s_nms[TOPN];
    __shared__ float  s_merged[TOPN];
    __shared__ int    s_gtbest[TOPN];
    __shared__ float4 s_gt4[NGT];
    __shared__ unsigned s_warp[32];
    __shared__ unsigned s_kalA[16], s_kalB[16];
    __shared__ int    s_ncur, s_m, s_M;

    const int b = blockIdx.x;
    const int t = threadIdx.x;
    const int lane = t & 31, wid = t >> 5;
    const int p    = t & (CHK - 1);   // candidate slot within chunk
    const int grp  = t >> 9;          // 0 or 1

    const float4* anc4 = (const float4*)(anchors) + (size_t)b * NPB;
    const float4* dlt4 = (const float4*)(deltas)  + (size_t)b * NPB;
    const float*  lab  = labels + (size_t)b * NPB;
    float4*   boxes = g_boxes + (size_t)b * NPB;
    unsigned* k30g  = g_k30  + (size_t)b * NPB;

    // ================= Phase A: decode + key30 + bucket histogram ==========
    #pragma unroll
    for (int c = 0; c < 4; ++c) s_hist[c * 1024 + t] = 0;
    if (t == 0) s_ncur = 0;
    __syncthreads();

    #pragma unroll 4
    for (int k = 0; k < PER_TH; ++k) {
        int i = t + k * THREADS;
        float4 a = anc4[i];
        float4 d = dlt4[i];
        float ah  = __fsub_rn(a.z, a.x);
        float aw  = __fsub_rn(a.w, a.y);
        float acy = __fadd_rn(a.x, __fmul_rn(0.5f, ah));
        float acx = __fadd_rn(a.y, __fmul_rn(0.5f, aw));
        float h   = __fmul_rn(expf(d.z), ah);
        float w   = __fmul_rn(expf(d.w), aw);
        float cy  = __fadd_rn(__fmul_rn(d.x, ah), acy);
        float cx  = __fadd_rn(__fmul_rn(d.y, aw), acx);
        float y1  = __fsub_rn(cy, __fmul_rn(0.5f, h));
        float x1  = __fsub_rn(cx, __fmul_rn(0.5f, w));
        boxes[i]  = make_float4(y1, x1, __fadd_rn(y1, h), __fadd_rn(x1, w));
        unsigned key30 = 0x3F7FFFFFu - __float_as_uint(lab[i]);
        k30g[i] = key30;
        atomicAdd(&s_hist[bucket_of(key30)], 1u);
    }
    __syncthreads();

    // ================= Phase B: exclusive scan of 4096 bucket counts =======
    {
        unsigned v[4], sum = 0;
        #pragma unroll
        for (int j = 0; j < 4; ++j) { v[j] = s_hist[t * 4 + j]; }
        unsigned e[4];
        #pragma unroll
        for (int j = 0; j < 4; ++j) { e[j] = sum; sum += v[j]; }
        unsigned x = sum;
        #pragma unroll
        for (int o = 1; o < 32; o <<= 1) {
            unsigned y = __shfl_up_sync(0xffffffffu, x, o);
            if (lane >= o) x += y;
        }
        if (lane == 31) s_warp[wid] = x;
        __syncthreads();
        if (t < 32) {
            unsigned wsum = s_warp[t], xx = wsum;
            #pragma unroll
            for (int o = 1; o < 32; o <<= 1) {
                unsigned y = __shfl_up_sync(0xffffffffu, xx, o);
                if (t >= o) xx += y;
            }
            s_warp[t] = xx - wsum;
        }
        __syncthreads();
        unsigned prefix = s_warp[wid] + (x - sum);
        #pragma unroll
        for (int j = 0; j < 4; ++j) s_cum[t * 4 + j] = prefix + e[j];
        if (t == THREADS - 1) s_cum[NBUCK] = prefix + sum;
        __syncthreads();
    }

    // ========== Phase C: slabs (placed gather -> bucket sort -> NMS) =======
    int base = 0;                          // running slab base (uniform)
    for (int slab = 0; slab < NSLAB; ++slab) {
        if (s_ncur >= TOPN) break;         // uniform (post-sync)
        if (t == 0) s_m = 0;
        #pragma unroll
        for (int c = 0; c < 4; ++c) s_bpos[c * 1024 + t] = 0;
        __syncthreads();

        // placed gather: element goes straight to its bucket's slab range
        #pragma unroll 4
        for (int k = 0; k < PER_TH; ++k) {
            int i = t + k * THREADS;
            unsigned key30 = k30g[i];
            unsigned bk = bucket_of(key30);
            if (s_cum[bk] / SLABSZ == (unsigned)slab) {
                int pos = (int)(s_cum[bk] - (unsigned)base) + (int)atomicAdd(&s_bpos[bk], 1u);
                s_key[pos] = ((unsigned long long)key30 << 16) | (unsigned)i;
                atomicAdd(&s_m, 1);
            }
        }
        __syncthreads();
        int m = s_m;
        for (int i = t; i < PPOW; i += THREADS)
            if (i >= m) s_key[i] = ~0ull;
        __syncthreads();

        // per-bucket insertion sort IN SMEM (keys unique => deterministic)
        #pragma unroll
        for (int c = 0; c < 4; ++c) {
            int bk = t + c * THREADS;
            if (s_cum[bk] / SLABSZ == (unsigned)slab) {
                int lo = (int)(s_cum[bk] - (unsigned)base);
                int n  = (int)s_bpos[bk];
                for (int i2 = lo + 1; i2 < lo + n; ++i2) {
                    unsigned long long v = s_key[i2];
                    int j2 = i2 - 1;
                    while (j2 >= lo && s_key[j2] > v) { s_key[j2 + 1] = s_key[j2]; --j2; }
                    s_key[j2 + 1] = v;
                }
            }
        }
        __syncthreads();

        // NMS over sorted slab in chunks of CHK
        for (int pos = 0; pos < m; pos += CHK) {
            if (s_ncur >= TOPN) break;        // uniform (post-sync)
            int nc = s_ncur;

            // ---- load candidate (both groups hold the same box) ----
            int ci = pos + p;
            bool valid = ci < m;
            float4 bx = make_float4(0.f, 0.f, 0.f, 0.f);
            float  ab = 0.f;
            if (valid) {
                unsigned gidx = (unsigned)(s_key[ci] & 0xFFFFu);
                bx = boxes[gidx];
                ab = __fmul_rn(__fsub_rn(bx.z, bx.x), __fsub_rn(bx.w, bx.y));
            }

            // ---- split prekill: grpA tests [0,ncA), grpB tests [ncA,nc) ----
            int ncA = (nc + 1) >> 1;
            int j0 = grp ? ncA : 0;
            int j1 = grp ? nc  : ncA;
            bool kill = !valid;
            if (valid) {
                for (int j = j0; j < j1 && !kill; ++j)
                    kill = suppress_test(s_sel[j], s_sela[j], bx, ab);
            }
            unsigned kb = __ballot_sync(0xffffffffu, kill);
            if (lane == 0) { if (grp == 0) s_kalA[wid] = kb; else s_kalB[wid - 16] = kb; }
            __syncthreads();

            // ---- merge kill info, compact alive (order-preserving) ----
            bool alive = false;
            if (grp == 0) {
                unsigned kw = s_kalA[p >> 5] | s_kalB[p >> 5];
                alive = valid && !((kw >> (p & 31)) & 1u);
            }
            unsigned bal = __ballot_sync(0xffffffffu, alive);
            if (lane == 0) s_warp[wid] = __popc(bal);
            __syncthreads();
            if (t < 32) {
                unsigned wsum = s_warp[t], xx = wsum;
                #pragma unroll
                for (int o = 1; o < 32; o <<= 1) {
                    unsigned y = __shfl_up_sync(0xffffffffu, xx, o);
                    if (t >= o) xx += y;
                }
                s_warp[t] = xx - wsum;
                if (t == 31) s_M = (int)xx;
            }
            __syncthreads();
            if (alive) {
                int cpos = (int)s_warp[wid] + __popc(bal & ((1u << lane) - 1u));
                s_kbox[cpos] = bx;
            }
            // zero suppression mask (512x16 words)
            #pragma unroll
            for (int w = 0; w < 8; ++w) s_mask[w * 1024 + t] = 0;
            __syncthreads();
            int M = s_M;
            if (M == 0) continue;             // uniform

            // ---- pair enumeration among compacted survivors ----
            if (M >= 2 && p < M) {
                int half = M >> 1;
                float4 P = s_kbox[p];
                float pa = __fmul_rn(__fsub_rn(P.z, P.x), __fsub_rn(P.w, P.y));
                for (int d = 1 + grp; d <= half; d += 2) {
                    int o = p + d; if (o >= M) o -= M;
                    int a = p < o ? p : o;    // earlier = suppressor
                    int c = p < o ? o : p;
                    float4 C = s_kbox[o];
                    float ca = __fmul_rn(__fsub_rn(C.z, C.x), __fsub_rn(C.w, C.y));
                    if (suppress_test(P, pa, C, ca))
                        atomicOr(&s_mask[a * 16 + (c >> 5)], 1u << (c & 31));
                }
            }
            __syncthreads();

            // ---- warp0 greedy resolution over the bitmask (no block BARs) --
            if (t < 32) {
                unsigned dead = 0;
                unsigned aliveW = 0;
                if (t < 16) {
                    int bb = t * 32;
                    int rem = M - bb;
                    aliveW = (rem >= 32) ? 0xffffffffu
                           : (rem > 0 ? ((1u << rem) - 1u) : 0u);
                }
                int n = nc;
                for (int w = 0; w < 16 && n < TOPN; ++w) {
                    unsigned cur = __shfl_sync(0xffffffffu, aliveW & ~dead, w);
                    while (cur && n < TOPN) {
                        int bitp = __ffs(cur) - 1;
                        int i = w * 32 + bitp;
                        cur &= cur - 1;
                        if (t == 0) {
                            float4 sb = s_kbox[i];
                            s_sel[n] = sb;
                            s_sela[n] = __fmul_rn(__fsub_rn(sb.z, sb.x),
                                                  __fsub_rn(sb.w, sb.y));
                        }
                        n++;
                        unsigned row = (t < 16) ? s_mask[i * 16 + t] : 0u;
                        dead |= row;
                        unsigned rw = __shfl_sync(0xffffffffu, row, w);
                        cur &= ~rw;
                    }
                }
                if (t == 0) s_ncur = n;
            }
            __syncthreads();
        }
        __syncthreads();
        base += m;                           // uniform (m read post-sync)
    }
    __syncthreads();
    const int nsel = s_ncur;

    // ================= Phase D: clip, select_rois, rank, emit ==============
    for (int j = t; j < TOPN; j += THREADS) {
        float4 bxo = make_float4(0.f, 0.f, 0.f, 0.f);
        if (j < nsel) {
            float4 vv = s_sel[j];
            bxo.x = fminf(fmaxf(vv.x, 0.f), 1.f);
            bxo.y = fminf(fmaxf(vv.y, 0.f), 1.f);
            bxo.z = fminf(fmaxf(vv.z, 0.f), 1.f);
            bxo.w = fminf(fmaxf(vv.w, 0.f), 1.f);
        }
        s_nms[j] = bxo;
    }
    for (int j = t; j < NGT; j += THREADS) {
        s_gt4[j] = ((const float4*)gt)[(size_t)b * NGT + j];
    }
    __syncthreads();

    if (t < TOPN) {
        float4 a = s_nms[t];
        float aa = __fmul_rn(__fsub_rn(a.z, a.x), __fsub_rn(a.w, a.y));
        float mg = -1.f; int bi = 0;
        #pragma unroll 4
        for (int g = 0; g < NGT; ++g) {
            float4 gb = s_gt4[g];
            float yy1 = fmaxf(a.x, gb.x);
            float xx1 = fmaxf(a.y, gb.y);
            float yy2 = fminf(a.z, gb.z);
            float xx2 = fminf(a.w, gb.w);
            float inter = __fmul_rn(fmaxf(__fsub_rn(yy2, yy1), 0.f),
                                    fmaxf(__fsub_rn(xx2, xx1), 0.f));
            float gba = __fmul_rn(__fsub_rn(gb.z, gb.x), __fsub_rn(gb.w, gb.y));
            float denom = __fadd_rn(__fsub_rn(__fadd_rn(aa, gba), inter), 1e-7f);
            float iou = __fdiv_rn(inter, denom);
            if (iou > mg) { mg = iou; bi = g; }
        }
        s_merged[t] = mg; s_gtbest[t] = bi;
    }
    __syncthreads();

    if (t < TOPN) {
        float mg = s_merged[t];
        int r = 0;
        for (int j = 0; j < TOPN; ++j) {
            float mj = s_merged[j];
            if (mj > mg || (mj == mg && j < t)) ++r;
        }
        if (r < TPOS) {
            float4 a = s_nms[t];
            float* roi = out + ((size_t)b * 128 + r) * 4;
            roi[0] = a.x; roi[1] = a.y; roi[2] = a.z; roi[3] = a.w;
            out[(size_t)BATCH * 128 * 4 + (size_t)b * TPOS + r] = (float)s_gtbest[t];
        }
    }
    for (int j = t; j < 64 * 4; j += THREADS) {
        out[((size_t)b * 128 + TPOS) * 4 + j] = 0.f;
    }
}

extern "C" void kernel_launch(void* const* d_in, const int* in_sizes, int n_in,
                              void* d_out, int out_size) {
    const float* deltas  = (const float*)d_in[0];
    const float* labels  = (const float*)d_in[1];
    const float* anchors = (const float*)d_in[2];
    const float* gt      = (const float*)d_in[3];
    float* out = (float*)d_out;
    cudaFuncSetAttribute(roi_kernel, cudaFuncAttributeMaxDynamicSharedMemorySize,
                         DYN_BYTES);
    roi_kernel<<<BATCH, THREADS, DYN_BYTES>>>(deltas, labels, anchors, gt, out);
}